// round 1
// baseline (speedup 1.0000x reference)
#include <cuda_runtime.h>

#define BB 1024
#define TT 2048
#define DD 16
#define UU 4
#define HH 128
#define MM 8            // batch rows per CTA
#define NTHREADS 128
#define W2_PITCH 130    // padded row pitch for W2^T (bank-conflict-free pair loads)

typedef unsigned long long u64;

// ---- f32x2 helpers (FFMA2 path: PTX-only on sm_103a) ----
__device__ __forceinline__ u64 pk2(float lo, float hi) {
    u64 r; asm("mov.b64 %0, {%1, %2};" : "=l"(r) : "f"(lo), "f"(hi)); return r;
}
__device__ __forceinline__ void upk2(u64 v, float& lo, float& hi) {
    asm("mov.b64 {%0, %1}, %2;" : "=f"(lo), "=f"(hi) : "l"(v));
}
__device__ __forceinline__ u64 ffma2(u64 a, u64 b, u64 c) {
    u64 d; asm("fma.rn.f32x2 %0, %1, %2, %3;" : "=l"(d) : "l"(a), "l"(b), "l"(c)); return d;
}

// tanh(x) = 1 - 2/(exp(2x)+1); saturates correctly at +-inf, abs err ~1e-7
__device__ __forceinline__ float fast_tanh(float x) {
    float e = __expf(2.0f * x);
    return 1.0f - __fdividef(2.0f, e + 1.0f);
}

// Shared memory layout (floats):
//  sW1   : HH*HH         = 16384   [i][j]
//  sW0   : (DD+UU)*HH    = 2560    [i][j]
//  sW2T  : DD*W2_PITCH   = 2080    [d][i], padded pitch
//  sb0   : 128
//  sb1   : 128
//  sb2   : 16
//  sIN   : (DD+UU)*MM    = 160     [i][m]  (rows 0..15 = y, 16..19 = x_t)
//  sH1   : HH*MM         = 1024    [j][m]
//  sH2   : MM*HH         = 1024    [m][j]
#define SMEM_FLOATS (16384 + 2560 + 2080 + 128 + 128 + 16 + 160 + 1024 + 1024)
#define SMEM_BYTES  (SMEM_FLOATS * 4)

__global__ void __launch_bounds__(NTHREADS, 1)
gnsde_kernel(const float* __restrict__ carry,
             const float* __restrict__ x,
             const float* __restrict__ noise,
             const float* __restrict__ W0,
             const float* __restrict__ b0,
             const float* __restrict__ W1,
             const float* __restrict__ b1,
             const float* __restrict__ W2,
             const float* __restrict__ b2,
             float* __restrict__ out)
{
    extern __shared__ float smem[];
    float* sW1  = smem;
    float* sW0  = sW1  + HH * HH;
    float* sW2T = sW0  + (DD + UU) * HH;
    float* sb0  = sW2T + DD * W2_PITCH;
    float* sb1  = sb0  + HH;
    float* sb2  = sb1  + HH;
    float* sIN  = sb2  + DD;
    float* sH1  = sIN  + (DD + UU) * MM;
    float* sH2  = sH1  + HH * MM;

    const int tid = threadIdx.x;
    const int b0r = blockIdx.x * MM;   // first batch row of this CTA

    // ---- stage weights ----
    for (int idx = tid; idx < HH * HH; idx += NTHREADS) sW1[idx] = W1[idx];
    for (int idx = tid; idx < (DD + UU) * HH; idx += NTHREADS) sW0[idx] = W0[idx];
    for (int idx = tid; idx < HH * DD; idx += NTHREADS) {
        int i = idx / DD, d = idx % DD;
        sW2T[d * W2_PITCH + i] = W2[idx];
    }
    if (tid < HH) { sb0[tid] = b0[tid]; sb1[tid] = b1[tid]; }
    if (tid < DD) sb2[tid] = b2[tid];

    // initial y from carry: sIN[d][m]
    for (int idx = tid; idx < DD * MM; idx += NTHREADS) {
        int m = idx % MM, d = idx / MM;
        sIN[d * MM + m] = carry[(size_t)(b0r + m) * DD + d];
    }
    // x(0)
    if (tid < MM) {
        float4 xv = *(const float4*)&x[((size_t)(b0r + tid) * TT + 0) * UU];
        sIN[(DD + 0) * MM + tid] = xv.x;
        sIN[(DD + 1) * MM + tid] = xv.y;
        sIN[(DD + 2) * MM + tid] = xv.z;
        sIN[(DD + 3) * MM + tid] = xv.w;
    }
    __syncthreads();

    const int j  = tid;          // hidden column role
    const int m_ = tid >> 4;     // mu role: batch row
    const int d_ = tid & 15;     // mu role: output dim

    const float alpha  = 0.1f;
    const float onema  = 1.0f - alpha;
    const float sqa    = sqrtf(0.1f);

    float* ys  = out;
    float* mts = out + (size_t)BB * TT * DD;
    float* mus = out + 2ull * BB * TT * DD;

    const float bj0 = sb0[j];
    const float bj1 = sb1[j];

    for (int t = 0; t < TT; ++t) {
        // ---- prefetch (hide DRAM latency behind the two GEMM phases) ----
        float nz = noise[((size_t)(b0r + m_) * TT + t) * DD + d_];
        float4 xnext = make_float4(0.f, 0.f, 0.f, 0.f);
        if (tid < MM && t + 1 < TT)
            xnext = *(const float4*)&x[((size_t)(b0r + tid) * TT + (t + 1)) * UU];

        // ---- layer 0: h1[j][m] = tanh(b0[j] + sum_i in[i][m] * W0[i][j]) ----
        u64 a0, a1, a2, a3;
        {
            u64 bb = pk2(bj0, bj0);
            a0 = bb; a1 = bb; a2 = bb; a3 = bb;
        }
        #pragma unroll
        for (int i = 0; i < DD + UU; ++i) {
            float w = sW0[i * HH + j];
            u64 ww = pk2(w, w);
            const u64* inr = (const u64*)&sIN[i * MM];
            a0 = ffma2(ww, inr[0], a0);
            a1 = ffma2(ww, inr[1], a1);
            a2 = ffma2(ww, inr[2], a2);
            a3 = ffma2(ww, inr[3], a3);
        }
        {
            float v0, v1, v2, v3, v4, v5, v6, v7;
            upk2(a0, v0, v1); upk2(a1, v2, v3); upk2(a2, v4, v5); upk2(a3, v6, v7);
            float4* dst = (float4*)&sH1[j * MM];
            dst[0] = make_float4(fast_tanh(v0), fast_tanh(v1), fast_tanh(v2), fast_tanh(v3));
            dst[1] = make_float4(fast_tanh(v4), fast_tanh(v5), fast_tanh(v6), fast_tanh(v7));
        }
        __syncthreads();

        // ---- layer 1: h2[m][j] = tanh(b1[j] + sum_i h1[i][m] * W1[i][j]) ----
        {
            u64 bb = pk2(bj1, bj1);
            a0 = bb; a1 = bb; a2 = bb; a3 = bb;
        }
        #pragma unroll 8
        for (int i = 0; i < HH; ++i) {
            float w = sW1[i * HH + j];
            u64 ww = pk2(w, w);
            const u64* h1r = (const u64*)&sH1[i * MM];
            a0 = ffma2(ww, h1r[0], a0);
            a1 = ffma2(ww, h1r[1], a1);
            a2 = ffma2(ww, h1r[2], a2);
            a3 = ffma2(ww, h1r[3], a3);
        }
        {
            float v0, v1, v2, v3, v4, v5, v6, v7;
            upk2(a0, v0, v1); upk2(a1, v2, v3); upk2(a2, v4, v5); upk2(a3, v6, v7);
            sH2[0 * HH + j] = fast_tanh(v0);
            sH2[1 * HH + j] = fast_tanh(v1);
            sH2[2 * HH + j] = fast_tanh(v2);
            sH2[3 * HH + j] = fast_tanh(v3);
            sH2[4 * HH + j] = fast_tanh(v4);
            sH2[5 * HH + j] = fast_tanh(v5);
            sH2[6 * HH + j] = fast_tanh(v6);
            sH2[7 * HH + j] = fast_tanh(v7);
        }
        __syncthreads();

        // ---- layer 2 + gate + noise: thread = (m_, d_) ----
        {
            u64 acc = pk2(0.0f, 0.0f);
            const float* h2row = &sH2[m_ * HH];
            const float* w2row = &sW2T[d_ * W2_PITCH];
            #pragma unroll 8
            for (int i2 = 0; i2 < HH / 2; ++i2) {
                u64 hp = *(const u64*)&h2row[2 * i2];
                u64 wp = *(const u64*)&w2row[2 * i2];
                acc = ffma2(hp, wp, acc);
            }
            float px, py; upk2(acc, px, py);
            float mt = px + py + sb2[d_];
            float y  = sIN[d_ * MM + m_];
            float mu = onema * y + alpha * mt;
            float yn = mu + sqa * nz;

            size_t base = ((size_t)(b0r + m_) * TT + t) * DD + d_;
            ys[base]  = yn;
            mts[base] = mt;
            mus[base] = mu;

            sIN[d_ * MM + m_] = yn;     // y for next step
        }
        // stage x(t+1)
        if (tid < MM && t + 1 < TT) {
            sIN[(DD + 0) * MM + tid] = xnext.x;
            sIN[(DD + 1) * MM + tid] = xnext.y;
            sIN[(DD + 2) * MM + tid] = xnext.z;
            sIN[(DD + 3) * MM + tid] = xnext.w;
        }
        __syncthreads();
    }
}

extern "C" void kernel_launch(void* const* d_in, const int* in_sizes, int n_in,
                              void* d_out, int out_size) {
    const float* carry = (const float*)d_in[0];
    const float* x     = (const float*)d_in[1];
    const float* noise = (const float*)d_in[2];
    const float* W0    = (const float*)d_in[3];
    const float* b0    = (const float*)d_in[4];
    const float* W1    = (const float*)d_in[5];
    const float* b1    = (const float*)d_in[6];
    const float* W2    = (const float*)d_in[7];
    const float* b2    = (const float*)d_in[8];
    float* out = (float*)d_out;

    cudaFuncSetAttribute(gnsde_kernel, cudaFuncAttributeMaxDynamicSharedMemorySize, SMEM_BYTES);
    gnsde_kernel<<<BB / MM, NTHREADS, SMEM_BYTES>>>(carry, x, noise, W0, b0, W1, b1, W2, b2, out);
}

// round 2
// speedup vs baseline: 1.1975x; 1.1975x over previous
#include <cuda_runtime.h>

#define BB 1024
#define TT 2048
#define DD 16
#define UU 4
#define HH 128
#define MM 8            // batch rows per CTA
#define NT 512          // threads per CTA (16 warps)
#define KQ1 32          // k-slice per thread, layer 1 (128/4)
#define KQ0 5           // k-slice per thread, layer 0 (20/4)
#define PP  18          // sPart row pitch in u64 (padded: conflict-free STS.128)
#define H2P 132         // padded row pitch (floats) for sH2 / sW2T

typedef unsigned long long u64;

// ---- f32x2 helpers (packed-FMA path: PTX-only on sm_103a) ----
__device__ __forceinline__ u64 pk2(float lo, float hi) {
    u64 r; asm("mov.b64 %0, {%1, %2};" : "=l"(r) : "f"(lo), "f"(hi)); return r;
}
__device__ __forceinline__ void upk2(u64 v, float& lo, float& hi) {
    asm("mov.b64 {%0, %1}, %2;" : "=f"(lo), "=f"(hi) : "l"(v));
}
__device__ __forceinline__ u64 ffma2(u64 a, u64 b, u64 c) {
    u64 d; asm("fma.rn.f32x2 %0, %1, %2, %3;" : "=l"(d) : "l"(a), "l"(b), "l"(c)); return d;
}
__device__ __forceinline__ u64 add2(u64 a, u64 b) {
    u64 c; asm("add.rn.f32x2 %0, %1, %2;" : "=l"(c) : "l"(a), "l"(b)); return c;
}
__device__ __forceinline__ float tanh_fast(float x) {
    float y; asm("tanh.approx.f32 %0, %1;" : "=f"(y) : "f"(x)); return y;
}

__global__ void __launch_bounds__(NT, 1)
gnsde_kernel(const float* __restrict__ carry,
             const float* __restrict__ x,
             const float* __restrict__ noise,
             const float* __restrict__ W0,
             const float* __restrict__ b0,
             const float* __restrict__ W1,
             const float* __restrict__ b1,
             const float* __restrict__ W2,
             const float* __restrict__ b2,
             float* __restrict__ out)
{
    // ~38 KB static shared
    __shared__ __align__(16) u64   sPart[HH * PP];       // k-split partial sums
    __shared__ u64                 b0d[HH], b1d[HH];     // biases pre-duplicated
    __shared__ __align__(16) float sH1[HH * MM];         // [k][m]
    __shared__ __align__(16) float sH2[MM * H2P];        // [m][k] padded
    __shared__ __align__(16) float sW2T[DD * H2P];       // [d][k] padded
    __shared__ __align__(16) float sIN[(DD + UU) * MM];  // [k][m]; rows 0..15=y, 16..19=x_t
    __shared__ float               sb2[DD];

    const int tid = threadIdx.x;
    const int b0r = blockIdx.x * MM;

    const int j  = tid & (HH - 1);   // partial phase: hidden column
    const int kq = tid >> 7;         // partial phase: k-quarter 0..3
    const int jr = tid >> 2;         // reduce phase: hidden column
    const int mp = tid & 3;          // reduce phase: m-pair 0..3
    const int mm = (tid >> 4) & 7;   // layer2 (tid<128): batch row
    const int dd = tid & 15;         // layer2: output dim

    // ---- weights into registers (persistent) ----
    float w1r[KQ1];
#pragma unroll
    for (int kk = 0; kk < KQ1; ++kk) w1r[kk] = W1[(kq * KQ1 + kk) * HH + j];
    float w0r[KQ0];
#pragma unroll
    for (int kk = 0; kk < KQ0; ++kk) w0r[kk] = W0[(kq * KQ0 + kk) * HH + j];

    // ---- stage small tensors into shared ----
    for (int idx = tid; idx < HH * DD; idx += NT) {
        int i = idx >> 4, d = idx & 15;
        sW2T[d * H2P + i] = W2[idx];               // W2 is [H][D] row-major
    }
    if (tid < HH) { b0d[tid] = pk2(b0[tid], b0[tid]); b1d[tid] = pk2(b1[tid], b1[tid]); }
    if (tid < DD) sb2[tid] = b2[tid];

    float yreg = 0.0f;
    if (tid < 128) {
        yreg = carry[(size_t)(b0r + mm) * DD + dd];
        sIN[dd * MM + mm] = yreg;
    }
    if (tid >= 384 && tid < 384 + MM) {
        int m = tid - 384;
        float4 xv = *(const float4*)&x[((size_t)(b0r + m) * TT) * UU];
        sIN[(DD + 0) * MM + m] = xv.x;
        sIN[(DD + 1) * MM + m] = xv.y;
        sIN[(DD + 2) * MM + m] = xv.z;
        sIN[(DD + 3) * MM + m] = xv.w;
    }
    __syncthreads();

    const float alpha = 0.1f;
    const float onema = 0.9f;
    const float sqa   = 0.31622776601683794f;

    float* ys  = out;
    float* mts = out + (size_t)BB * TT * DD;
    float* mus = out + 2ull * BB * TT * DD;

    for (int t = 0; t < TT; ++t) {
        // ---- prefetch global data for this step (consumed at step end) ----
        float nz = 0.0f;
        if (tid < 128) nz = noise[((size_t)(b0r + mm) * TT + t) * DD + dd];
        float4 xn = make_float4(0.f, 0.f, 0.f, 0.f);
        const bool xp = (tid >= 384 && tid < 384 + MM) && (t + 1 < TT);
        if (xp) xn = *(const float4*)&x[((size_t)(b0r + (tid - 384)) * TT + (t + 1)) * UU];

        // ---- layer 0 partial: thread (j, kq), k = kq*5 .. kq*5+4 ----
        {
            u64 a0 = 0, a1 = 0, a2 = 0, a3 = 0;
#pragma unroll
            for (int kk = 0; kk < KQ0; ++kk) {
                const int k = kq * KQ0 + kk;
                u64 wd = pk2(w0r[kk], w0r[kk]);
                ulonglong2 hA = *(const ulonglong2*)&sIN[k * MM];      // m 0..3
                ulonglong2 hB = *(const ulonglong2*)&sIN[k * MM + 4];  // m 4..7
                a0 = ffma2(wd, hA.x, a0); a1 = ffma2(wd, hA.y, a1);
                a2 = ffma2(wd, hB.x, a2); a3 = ffma2(wd, hB.y, a3);
            }
            ulonglong2 p0; p0.x = a0; p0.y = a1;
            ulonglong2 p1; p1.x = a2; p1.y = a3;
            *(ulonglong2*)&sPart[j * PP + kq * 4]     = p0;
            *(ulonglong2*)&sPart[j * PP + kq * 4 + 2] = p1;
        }
        __syncthreads();

        // ---- layer 0 reduce (4 partials) + bias + tanh -> sH1[k][m] ----
        {
            u64 s = add2(add2(sPart[jr * PP + mp],     sPart[jr * PP + 4 + mp]),
                         add2(sPart[jr * PP + 8 + mp], sPart[jr * PP + 12 + mp]));
            s = add2(s, b0d[jr]);
            float lo, hi; upk2(s, lo, hi);
            *(u64*)&sH1[jr * MM + 2 * mp] = pk2(tanh_fast(lo), tanh_fast(hi));
        }
        __syncthreads();

        // ---- layer 1 partial: thread (j, kq), k = kq*32 .. +31, weights in regs ----
        {
            u64 a0 = 0, a1 = 0, a2 = 0, a3 = 0;
            const float* h1p = &sH1[kq * KQ1 * MM];
#pragma unroll
            for (int kk = 0; kk < KQ1; ++kk) {
                u64 wd = pk2(w1r[kk], w1r[kk]);
                ulonglong2 hA = *(const ulonglong2*)&h1p[kk * MM];
                ulonglong2 hB = *(const ulonglong2*)&h1p[kk * MM + 4];
                a0 = ffma2(wd, hA.x, a0); a1 = ffma2(wd, hA.y, a1);
                a2 = ffma2(wd, hB.x, a2); a3 = ffma2(wd, hB.y, a3);
            }
            ulonglong2 p0; p0.x = a0; p0.y = a1;
            ulonglong2 p1; p1.x = a2; p1.y = a3;
            *(ulonglong2*)&sPart[j * PP + kq * 4]     = p0;
            *(ulonglong2*)&sPart[j * PP + kq * 4 + 2] = p1;
        }
        __syncthreads();

        // ---- layer 1 reduce + bias + tanh -> sH2[m][k] (padded) ----
        {
            u64 s = add2(add2(sPart[jr * PP + mp],     sPart[jr * PP + 4 + mp]),
                         add2(sPart[jr * PP + 8 + mp], sPart[jr * PP + 12 + mp]));
            s = add2(s, b1d[jr]);
            float lo, hi; upk2(s, lo, hi);
            sH2[(2 * mp)     * H2P + jr] = tanh_fast(lo);
            sH2[(2 * mp + 1) * H2P + jr] = tanh_fast(hi);
        }
        __syncthreads();

        // ---- layer 2 + gate + noise + outputs: threads 0..127 = (mm, dd) ----
        if (tid < 128) {
            u64 acc0 = 0, acc1 = 0;
            const float* hrow = &sH2[mm * H2P];
            const float* wrow = &sW2T[dd * H2P];
#pragma unroll
            for (int i = 0; i < HH / 4; ++i) {
                ulonglong2 hp = *(const ulonglong2*)&hrow[4 * i];
                ulonglong2 wp = *(const ulonglong2*)&wrow[4 * i];
                acc0 = ffma2(hp.x, wp.x, acc0);
                acc1 = ffma2(hp.y, wp.y, acc1);
            }
            float lo, hi; upk2(add2(acc0, acc1), lo, hi);
            float mt = lo + hi + sb2[dd];
            float mu = onema * yreg + alpha * mt;
            float yn = mu + sqa * nz;

            size_t base = ((size_t)(b0r + mm) * TT + t) * DD + dd;
            ys[base]  = yn;
            mts[base] = mt;
            mus[base] = mu;

            yreg = yn;
            sIN[dd * MM + mm] = yn;     // publish y for next step's layer 0
        } else if (xp) {
            int m = tid - 384;
            sIN[(DD + 0) * MM + m] = xn.x;
            sIN[(DD + 1) * MM + m] = xn.y;
            sIN[(DD + 2) * MM + m] = xn.z;
            sIN[(DD + 3) * MM + m] = xn.w;
        }
        __syncthreads();
    }
}

extern "C" void kernel_launch(void* const* d_in, const int* in_sizes, int n_in,
                              void* d_out, int out_size) {
    const float* carry = (const float*)d_in[0];
    const float* x     = (const float*)d_in[1];
    const float* noise = (const float*)d_in[2];
    const float* W0    = (const float*)d_in[3];
    const float* b0    = (const float*)d_in[4];
    const float* W1    = (const float*)d_in[5];
    const float* b1    = (const float*)d_in[6];
    const float* W2    = (const float*)d_in[7];
    const float* b2    = (const float*)d_in[8];
    float* out = (float*)d_out;

    gnsde_kernel<<<BB / MM, NT>>>(carry, x, noise, W0, b0, W1, b1, W2, b2, out);
}